// round 1
// baseline (speedup 1.0000x reference)
#include <cuda_runtime.h>

#define B_  2
#define L_  2048
#define D_  1024
#define H_  16
#define HD_ 64
#define MROWS (B_ * L_)   // 4096

// ---------------- scratch (static device globals; no allocation allowed) ----
__device__ float g_Q[B_ * H_ * L_ * HD_];   // [B,H,L,HD]
__device__ float g_K[B_ * H_ * L_ * HD_];
__device__ float g_V[B_ * H_ * L_ * HD_];
__device__ float g_ctx[B_ * L_ * D_];       // [B,L,D] attention output pre-Wo

// ============================================================================
// Tiled SGEMM: Out[M,N] = X[M,K] @ W[K,N] + bias[N]
// M=4096, N=K=1024. Block tile 128x128, 256 threads, 8x8 micro, K-tile 8.
// HEADOUT=true writes Out into [B,H,L,HD] layout (for Q/K/V projections).
// ============================================================================
template <bool HEADOUT>
__global__ __launch_bounds__(256, 2)
void gemm_bias_kernel(const float* __restrict__ X,
                      const float* __restrict__ W,
                      const float* __restrict__ bias,
                      float* __restrict__ Out)
{
    __shared__ float As[8][128];   // A transposed: As[k][m]
    __shared__ float Bs[8][128];   // Bs[k][n]

    const int tid = threadIdx.x;
    const int ttx = tid & 15;          // 0..15  -> 8 output cols
    const int tty = tid >> 4;          // 0..15  -> 8 output rows
    const int rowBase = blockIdx.y * 128;
    const int colBase = blockIdx.x * 128;

    float acc[8][8];
#pragma unroll
    for (int i = 0; i < 8; i++)
#pragma unroll
        for (int j = 0; j < 8; j++) acc[i][j] = 0.f;

    // A-tile load mapping: 128 rows x 8 k-cols, one float4 per thread
    const int aRow  = tid >> 1;            // 0..127
    const int aCol4 = (tid & 1) * 4;       // 0 or 4
    const float* Aptr = X + (size_t)(rowBase + aRow) * D_ + aCol4;
    // B-tile load mapping: 8 k-rows x 128 cols, one float4 per thread
    const int bRow = tid >> 5;             // 0..7
    const int bCol = (tid & 31) * 4;       // 0..124
    const float* Bptr = W + (size_t)bRow * D_ + colBase + bCol;

    for (int k0 = 0; k0 < D_; k0 += 8) {
        float4 av = *(const float4*)(Aptr + k0);
        float4 bv = *(const float4*)(Bptr + (size_t)k0 * D_);
        As[aCol4 + 0][aRow] = av.x;
        As[aCol4 + 1][aRow] = av.y;
        As[aCol4 + 2][aRow] = av.z;
        As[aCol4 + 3][aRow] = av.w;
        *(float4*)&Bs[bRow][bCol] = bv;
        __syncthreads();

#pragma unroll
        for (int k = 0; k < 8; k++) {
            float4 a0 = *(const float4*)&As[k][tty * 8];
            float4 a1 = *(const float4*)&As[k][tty * 8 + 4];
            float4 b0 = *(const float4*)&Bs[k][ttx * 8];
            float4 b1 = *(const float4*)&Bs[k][ttx * 8 + 4];
            float a[8] = {a0.x, a0.y, a0.z, a0.w, a1.x, a1.y, a1.z, a1.w};
            float b[8] = {b0.x, b0.y, b0.z, b0.w, b1.x, b1.y, b1.z, b1.w};
#pragma unroll
            for (int i = 0; i < 8; i++)
#pragma unroll
                for (int j = 0; j < 8; j++)
                    acc[i][j] += a[i] * b[j];
        }
        __syncthreads();
    }

    const int row0 = rowBase + tty * 8;
    const int col0 = colBase + ttx * 8;
    float4 bia0 = *(const float4*)(bias + col0);
    float4 bia1 = *(const float4*)(bias + col0 + 4);
    float bi[8] = {bia0.x, bia0.y, bia0.z, bia0.w, bia1.x, bia1.y, bia1.z, bia1.w};

#pragma unroll
    for (int i = 0; i < 8; i++) {
        const int m = row0 + i;
#pragma unroll
        for (int jj = 0; jj < 8; jj += 4) {
            float4 v;
            v.x = acc[i][jj + 0] + bi[jj + 0];
            v.y = acc[i][jj + 1] + bi[jj + 1];
            v.z = acc[i][jj + 2] + bi[jj + 2];
            v.w = acc[i][jj + 3] + bi[jj + 3];
            if (HEADOUT) {
                const int b = m >> 11;              // m / L
                const int l = m & (L_ - 1);
                const int n = col0 + jj;
                const int h = n >> 6;               // n / HD
                const int d = n & (HD_ - 1);
                float* dst = Out + ((size_t)((b * H_ + h) * L_ + l)) * HD_ + d;
                *(float4*)dst = v;
            } else {
                *(float4*)(Out + (size_t)m * D_ + col0 + jj) = v;
            }
        }
    }
}

// ============================================================================
// Flash attention (fp32): per block: one (b,h) and a 64-row query tile.
// Online softmax over key tiles of 64. K stored TRANSPOSED in smem (dim-major)
// so both GEMM phases do conflict-free float4 reads. K/V share one buffer.
// Thread layout: 128 thr = (ty 0..15) x (tx 0..7); micro-tile:
//   rows r_i = 16*i + ty (i=0..3), cols c_j = 8*tx + j (j=0..7).
// ============================================================================
#define BM 64
#define BK 64
#define SS 68   // smem row stride (floats): 68 % 4 == 0, 68 % 32 == 4 -> no conflicts

__global__ __launch_bounds__(128)
void attn_kernel(const float* __restrict__ Q, const float* __restrict__ K,
                 const float* __restrict__ V, float* __restrict__ ctx)
{
    extern __shared__ float sm[];
    float* Qs  = sm;               // [64][SS]  Q tile, pre-scaled by 1/8
    float* KVs = sm + 64 * SS;     // [64][SS]  K^T (dim-major), then V (key-major)
    float* Ps  = sm + 2 * 64 * SS; // [64][SS]  softmax probabilities

    const int tid = threadIdx.x;
    const int tx = tid & 7;
    const int ty = tid >> 3;
    const int bh = blockIdx.y;                 // b*H + h
    const int q0 = blockIdx.x * BM;

    const float* Qg = Q + ((size_t)bh * L_ + q0) * HD_;
    const float* Kg = K + (size_t)bh * L_ * HD_;
    const float* Vg = V + (size_t)bh * L_ * HD_;

    // ---- load Q tile (scaled by 1/sqrt(HD) = 0.125) ----
    for (int f = tid; f < 64 * 16; f += 128) {
        const int r = f >> 4, c4 = (f & 15) << 2;
        float4 v = *(const float4*)(Qg + r * HD_ + c4);
        v.x *= 0.125f; v.y *= 0.125f; v.z *= 0.125f; v.w *= 0.125f;
        *(float4*)&Qs[r * SS + c4] = v;
    }

    float o[4][8];
    float m_i[4], l_i[4];
#pragma unroll
    for (int i = 0; i < 4; i++) {
        m_i[i] = -1e30f;
        l_i[i] = 0.f;
#pragma unroll
        for (int j = 0; j < 8; j++) o[i][j] = 0.f;
    }

    for (int k0 = 0; k0 < L_; k0 += BK) {
        __syncthreads();   // prior PV reads done (and Q stores visible on iter 0)

        // ---- load K tile transposed: KVs[dim][key] ----
        for (int f = tid; f < 64 * 16; f += 128) {
            const int r = f >> 4, c4 = (f & 15) << 2;    // key r, dims c4..c4+3
            float4 v = *(const float4*)(Kg + (size_t)(k0 + r) * HD_ + c4);
            KVs[(c4 + 0) * SS + r] = v.x;
            KVs[(c4 + 1) * SS + r] = v.y;
            KVs[(c4 + 2) * SS + r] = v.z;
            KVs[(c4 + 3) * SS + r] = v.w;
        }
        __syncthreads();

        // ---- S = Qs @ K^T  (s[i][j] over rows r_i, key-cols c_j) ----
        float s[4][8];
#pragma unroll
        for (int i = 0; i < 4; i++)
#pragma unroll
            for (int j = 0; j < 8; j++) s[i][j] = 0.f;

#pragma unroll 4
        for (int kk4 = 0; kk4 < 16; kk4++) {
            float qv[4][4];
#pragma unroll
            for (int i = 0; i < 4; i++) {
                float4 t = *(const float4*)&Qs[(16 * i + ty) * SS + kk4 * 4];
                qv[i][0] = t.x; qv[i][1] = t.y; qv[i][2] = t.z; qv[i][3] = t.w;
            }
#pragma unroll
            for (int qq = 0; qq < 4; qq++) {
                const int dim = kk4 * 4 + qq;
                float4 b0 = *(const float4*)&KVs[dim * SS + tx * 8];
                float4 b1 = *(const float4*)&KVs[dim * SS + tx * 8 + 4];
                float kb[8] = {b0.x, b0.y, b0.z, b0.w, b1.x, b1.y, b1.z, b1.w};
#pragma unroll
                for (int i = 0; i < 4; i++)
#pragma unroll
                    for (int j = 0; j < 8; j++)
                        s[i][j] += qv[i][qq] * kb[j];
            }
        }

        // ---- online softmax on register tile ----
#pragma unroll
        for (int i = 0; i < 4; i++) {
            float rm = s[i][0];
#pragma unroll
            for (int j = 1; j < 8; j++) rm = fmaxf(rm, s[i][j]);
#pragma unroll
            for (int off = 1; off < 8; off <<= 1)
                rm = fmaxf(rm, __shfl_xor_sync(0xffffffffu, rm, off));
            const float mn = fmaxf(m_i[i], rm);
            const float corr = __expf(m_i[i] - mn);
            m_i[i] = mn;
            float rs = 0.f;
#pragma unroll
            for (int j = 0; j < 8; j++) {
                s[i][j] = __expf(s[i][j] - mn);
                rs += s[i][j];
            }
#pragma unroll
            for (int off = 1; off < 8; off <<= 1)
                rs += __shfl_xor_sync(0xffffffffu, rs, off);
            l_i[i] = l_i[i] * corr + rs;
#pragma unroll
            for (int j = 0; j < 8; j++) o[i][j] *= corr;
        }

        __syncthreads();   // everyone done reading K^T before overwrite with V

        // ---- write P to smem; load V tile (key-major) into KVs ----
#pragma unroll
        for (int i = 0; i < 4; i++) {
            float4 p0 = {s[i][0], s[i][1], s[i][2], s[i][3]};
            float4 p1 = {s[i][4], s[i][5], s[i][6], s[i][7]};
            *(float4*)&Ps[(16 * i + ty) * SS + tx * 8]     = p0;
            *(float4*)&Ps[(16 * i + ty) * SS + tx * 8 + 4] = p1;
        }
        for (int f = tid; f < 64 * 16; f += 128) {
            const int r = f >> 4, c4 = (f & 15) << 2;
            *(float4*)&KVs[r * SS + c4] =
                *(const float4*)(Vg + (size_t)(k0 + r) * HD_ + c4);
        }
        __syncthreads();

        // ---- O += P @ V ----
#pragma unroll 4
        for (int kk4 = 0; kk4 < 16; kk4++) {
            float pv[4][4];
#pragma unroll
            for (int i = 0; i < 4; i++) {
                float4 t = *(const float4*)&Ps[(16 * i + ty) * SS + kk4 * 4];
                pv[i][0] = t.x; pv[i][1] = t.y; pv[i][2] = t.z; pv[i][3] = t.w;
            }
#pragma unroll
            for (int qq = 0; qq < 4; qq++) {
                const int kk = kk4 * 4 + qq;
                float4 v0 = *(const float4*)&KVs[kk * SS + tx * 8];
                float4 v1 = *(const float4*)&KVs[kk * SS + tx * 8 + 4];
                float vb[8] = {v0.x, v0.y, v0.z, v0.w, v1.x, v1.y, v1.z, v1.w};
#pragma unroll
                for (int i = 0; i < 4; i++)
#pragma unroll
                    for (int j = 0; j < 8; j++)
                        o[i][j] += pv[i][qq] * vb[j];
            }
        }
    }

    // ---- epilogue: normalize, write ctx[B,L,D] with head interleave ----
    const int b = bh / H_;
    const int h = bh % H_;
#pragma unroll
    for (int i = 0; i < 4; i++) {
        const float inv = 1.f / l_i[i];
        const int r = q0 + 16 * i + ty;
        float* dst = ctx + ((size_t)(b * L_ + r)) * D_ + h * HD_ + tx * 8;
        float4 w0 = {o[i][0] * inv, o[i][1] * inv, o[i][2] * inv, o[i][3] * inv};
        float4 w1 = {o[i][4] * inv, o[i][5] * inv, o[i][6] * inv, o[i][7] * inv};
        *(float4*)dst       = w0;
        *(float4*)(dst + 4) = w1;
    }
}

// ============================================================================
// launch
// ============================================================================
extern "C" void kernel_launch(void* const* d_in, const int* in_sizes, int n_in,
                              void* d_out, int out_size)
{
    const float* query = (const float*)d_in[0];
    const float* key_  = (const float*)d_in[1];
    const float* value = (const float*)d_in[2];
    const float* Wq = (const float*)d_in[3];
    const float* bq = (const float*)d_in[4];
    const float* Wk = (const float*)d_in[5];
    const float* bk = (const float*)d_in[6];
    const float* Wv = (const float*)d_in[7];
    const float* bv = (const float*)d_in[8];
    const float* Wo = (const float*)d_in[9];
    const float* bo = (const float*)d_in[10];
    float* out = (float*)d_out;

    float *Qd, *Kd, *Vd, *Ctx;
    cudaGetSymbolAddress((void**)&Qd,  g_Q);
    cudaGetSymbolAddress((void**)&Kd,  g_K);
    cudaGetSymbolAddress((void**)&Vd,  g_V);
    cudaGetSymbolAddress((void**)&Ctx, g_ctx);

    const size_t attn_smem = 3 * 64 * SS * sizeof(float);   // 52224 B
    cudaFuncSetAttribute(attn_kernel,
                         cudaFuncAttributeMaxDynamicSharedMemorySize,
                         (int)attn_smem);

    dim3 ggrid(D_ / 128, MROWS / 128);   // (8, 32)
    gemm_bias_kernel<true ><<<ggrid, 256>>>(query, Wq, bq, Qd);
    gemm_bias_kernel<true ><<<ggrid, 256>>>(key_,  Wk, bk, Kd);
    gemm_bias_kernel<true ><<<ggrid, 256>>>(value, Wv, bv, Vd);

    dim3 agrid(L_ / BM, B_ * H_);        // (32, 32)
    attn_kernel<<<agrid, 128, attn_smem>>>(Qd, Kd, Vd, Ctx);

    gemm_bias_kernel<false><<<ggrid, 256>>>(Ctx, Wo, bo, out);
}

// round 3
// speedup vs baseline: 3.1427x; 3.1427x over previous
#include <cuda_runtime.h>
#include <cuda_bf16.h>
#include <cstdint>

#define B_  2
#define L_  2048
#define D_  1024
#define H_  16
#define HD_ 64
#define MROWS 4096
#define KSPLIT 3072

// ---------------- scratch (static device globals; no allocation allowed) ----
__device__ __nv_bfloat16 g_A[MROWS * KSPLIT];        // split-concat activations
__device__ __nv_bfloat16 g_Wt[4][D_ * KSPLIT];       // split-concat transposed weights
__device__ __nv_bfloat16 g_Qh[B_*H_*L_*HD_], g_Ql[B_*H_*L_*HD_];
__device__ __nv_bfloat16 g_Kh[B_*H_*L_*HD_], g_Kl[B_*H_*L_*HD_];
__device__ __nv_bfloat16 g_Vh[B_*H_*L_*HD_], g_Vl[B_*H_*L_*HD_];
__device__ float g_ctx[B_ * L_ * D_];

// ============================================================================
// helpers
// ============================================================================
__device__ __forceinline__ uint32_t smem_u32(const void* p) {
    uint32_t a;
    asm("{ .reg .u64 t; cvta.to.shared.u64 t, %1; cvt.u32.u64 %0, t; }" : "=r"(a) : "l"(p));
    return a;
}
__device__ __forceinline__ void cp16(uint32_t dst, const void* src) {
    asm volatile("cp.async.cg.shared.global [%0], [%1], 16;" :: "r"(dst), "l"(src));
}
#define CPCOMMIT() asm volatile("cp.async.commit_group;" ::: "memory")
#define CPWAIT(n)  asm volatile("cp.async.wait_group %0;" :: "n"(n) : "memory")

__device__ __forceinline__ void ldsm4(uint32_t r[4], uint32_t addr) {
    asm volatile("ldmatrix.sync.aligned.m8n8.x4.shared.b16 {%0,%1,%2,%3}, [%4];"
        : "=r"(r[0]), "=r"(r[1]), "=r"(r[2]), "=r"(r[3]) : "r"(addr));
}
__device__ __forceinline__ void ldsm4t(uint32_t r[4], uint32_t addr) {
    asm volatile("ldmatrix.sync.aligned.m8n8.x4.trans.shared.b16 {%0,%1,%2,%3}, [%4];"
        : "=r"(r[0]), "=r"(r[1]), "=r"(r[2]), "=r"(r[3]) : "r"(addr));
}
__device__ __forceinline__ void mma16816(float c[4], const uint32_t a[4],
                                         uint32_t b0, uint32_t b1) {
    asm volatile("mma.sync.aligned.m16n8k16.row.col.f32.bf16.bf16.f32 "
        "{%0,%1,%2,%3}, {%4,%5,%6,%7}, {%8,%9}, {%0,%1,%2,%3};"
        : "+f"(c[0]), "+f"(c[1]), "+f"(c[2]), "+f"(c[3])
        : "r"(a[0]), "r"(a[1]), "r"(a[2]), "r"(a[3]), "r"(b0), "r"(b1));
}
// pack: result = [hiVal(bf16) | loVal(bf16)], loVal in low 16 bits (element k)
__device__ __forceinline__ uint32_t pack_bf2(float hiVal, float loVal) {
    uint32_t r;
    asm("cvt.rn.bf16x2.f32 %0, %1, %2;" : "=r"(r) : "f"(hiVal), "f"(loVal));
    return r;
}

// ============================================================================
// split conversions (unchanged from R1)
// A'[m, 0:1024)=hi, [1024:2048)=lo, [2048:3072)=hi
// Wt'[n, 0:1024)=hi, [1024:2048)=hi, [2048:3072)=lo
// ============================================================================
__global__ void split_rows(const float* __restrict__ X, __nv_bfloat16* __restrict__ A)
{
    const int idx = blockIdx.x * 256 + threadIdx.x;
    const int r = idx >> 8;
    const int c = (idx & 255) << 2;
    float4 v = *(const float4*)(X + (size_t)r * D_ + c);
    float vf[4] = {v.x, v.y, v.z, v.w};
    ushort4 hv, lv;
    unsigned short* hp = &hv.x;
    unsigned short* lp = &lv.x;
#pragma unroll
    for (int j = 0; j < 4; j++) {
        __nv_bfloat16 hi = __float2bfloat16(vf[j]);
        __nv_bfloat16 lo = __float2bfloat16(vf[j] - __bfloat162float(hi));
        hp[j] = __bfloat16_as_ushort(hi);
        lp[j] = __bfloat16_as_ushort(lo);
    }
    __nv_bfloat16* row = A + (size_t)r * KSPLIT;
    *(ushort4*)(row + c)        = hv;
    *(ushort4*)(row + D_ + c)   = lv;
    *(ushort4*)(row + 2*D_ + c) = hv;
}

__global__ void split_weightT(const float* __restrict__ W, __nv_bfloat16* __restrict__ Wt)
{
    __shared__ float t[32][33];
    const int k0 = blockIdx.x * 32, n0 = blockIdx.y * 32;
    const int tx = threadIdx.x, ty = threadIdx.y;
    for (int i = ty; i < 32; i += 8)
        t[i][tx] = W[(size_t)(k0 + i) * D_ + n0 + tx];
    __syncthreads();
    for (int i = ty; i < 32; i += 8) {
        const float x = t[tx][i];
        __nv_bfloat16 hi = __float2bfloat16(x);
        __nv_bfloat16 lo = __float2bfloat16(x - __bfloat162float(hi));
        __nv_bfloat16* row = Wt + (size_t)(n0 + i) * KSPLIT + k0 + tx;
        row[0]    = hi;
        row[D_]   = hi;
        row[2*D_] = lo;
    }
}

// ============================================================================
// mma.sync GEMM: C[M=4096, N=1024] = A'[M,3072] x Wt'[N,3072]^T (+bias)(*scale)
// CTA 256x128, 512 threads (16 warps, 4x4), warp tile 64x32, K-chunk 64,
// 3-stage cp.async pipeline, XOR-swizzled smem.
// MODE 0: fp32 out [M,D]. MODE 1: bf16 hi/lo head-layout out [B,H,L,HD].
// ============================================================================
#define G_STAGE 49152               // A 32KB + B 16KB
#define G_SMEM  (3 * G_STAGE)       // 147456

template <int MODE>
__global__ __launch_bounds__(512, 1)
void gemm_mma(const __nv_bfloat16* __restrict__ A, const __nv_bfloat16* __restrict__ Bt,
              const float* __restrict__ bias, float* __restrict__ OutF,
              __nv_bfloat16* __restrict__ OutH, __nv_bfloat16* __restrict__ OutL,
              float scale)
{
    extern __shared__ __align__(128) char smem[];
    const uint32_t sb = smem_u32(smem);
    const int tid = threadIdx.x, lane = tid & 31, warp = tid >> 5;
    const int wm = warp >> 2, wn = warp & 3;
    const int rowBase = blockIdx.y * 256;
    const int colBase = blockIdx.x * 128;

    float c[4][4][4];
#pragma unroll
    for (int i = 0; i < 4; i++)
#pragma unroll
        for (int j = 0; j < 4; j++)
#pragma unroll
            for (int k = 0; k < 4; k++) c[i][j][k] = 0.f;

    const int lr = tid >> 3, lg = tid & 7;     // load row/granule pieces

    auto issue = [&](int chunk, int s) {
        const uint32_t SA = sb + s * G_STAGE, SB = SA + 32768;
        const int c0 = chunk * 64;
#pragma unroll
        for (int j = 0; j < 4; j++) {          // A: 256 rows x 8 granules
            const int r = 64 * j + lr;
            cp16(SA + r * 128 + ((lg ^ (r & 7)) << 4),
                 A + (size_t)(rowBase + r) * KSPLIT + c0 + lg * 8);
        }
#pragma unroll
        for (int j = 0; j < 2; j++) {          // B: 128 rows x 8 granules
            const int r = 64 * j + lr;
            cp16(SB + r * 128 + ((lg ^ (r & 7)) << 4),
                 Bt + (size_t)(colBase + r) * KSPLIT + c0 + lg * 8);
        }
    };

    issue(0, 0); CPCOMMIT();
    issue(1, 1); CPCOMMIT();

    for (int ch = 0; ch < 48; ch++) {
        __syncthreads();                        // all warps done with stage (ch+2)%3
        if (ch + 2 < 48) issue(ch + 2, (ch + 2) % 3);
        CPCOMMIT();
        CPWAIT(2);                              // stage ch%3 ready
        __syncthreads();

        const uint32_t SA = sb + (ch % 3) * G_STAGE, SB = SA + 32768;
#pragma unroll
        for (int kk = 0; kk < 4; kk++) {
            const int g = 2 * kk + (lane >> 4);
            uint32_t af[4][4];
#pragma unroll
            for (int mt = 0; mt < 4; mt++) {
                const int r = 64 * wm + 16 * mt + (lane & 15);
                ldsm4(af[mt], SA + r * 128 + ((g ^ (r & 7)) << 4));
            }
#pragma unroll
            for (int ntp = 0; ntp < 2; ntp++) {
                uint32_t bf[4];
                const int r = 32 * wn + 16 * ntp + (lane & 15);
                ldsm4(bf, SB + r * 128 + ((g ^ (r & 7)) << 4));
#pragma unroll
                for (int mt = 0; mt < 4; mt++) {
                    mma16816(c[mt][2*ntp],   af[mt], bf[0], bf[2]);
                    mma16816(c[mt][2*ntp+1], af[mt], bf[1], bf[3]);
                }
            }
        }
    }

    // epilogue
#pragma unroll
    for (int mt = 0; mt < 4; mt++)
#pragma unroll
        for (int nt = 0; nt < 4; nt++) {
            const int n0 = colBase + 32 * wn + 8 * nt + (lane & 3) * 2;
            const float b0v = bias[n0], b1v = bias[n0 + 1];
#pragma unroll
            for (int h = 0; h < 2; h++) {
                const int m = rowBase + 64 * wm + 16 * mt + 8 * h + (lane >> 2);
                float v0 = c[mt][nt][2*h]   + b0v;
                float v1 = c[mt][nt][2*h+1] + b1v;
                if (MODE == 1) {
                    v0 *= scale; v1 *= scale;
                    const uint32_t hi = pack_bf2(v1, v0);
                    const float f0 = __uint_as_float(hi << 16);
                    const float f1 = __uint_as_float(hi & 0xffff0000u);
                    const uint32_t lo = pack_bf2(v1 - f1, v0 - f0);
                    const int bb = m >> 11, l = m & (L_ - 1);
                    const int hh = n0 >> 6, d = n0 & (HD_ - 1);
                    const size_t idx = ((size_t)(bb * H_ + hh) * L_ + l) * HD_ + d;
                    *(uint32_t*)((char*)OutH + idx * 2) = hi;
                    *(uint32_t*)((char*)OutL + idx * 2) = lo;
                } else {
                    float2 v = {v0, v1};
                    *(float2*)(OutF + (size_t)m * D_ + n0) = v;
                }
            }
        }
}

// ============================================================================
// Flash attention with mma.sync + register-resident P (FA2 style).
// CTA: 128 q-rows, 4 warps (warp = 32 q-rows). Key tiles of 64, double-buffered.
// S = Qh*Kh + Ql*Kh + Qh*Kl ; O += Ph*Vh + Pl*Vh + Ph*Vl (all bf16 mma, fp32 acc)
// SMEM: Qh/Ql [128][64], Kh/Kl/Vh/Vl [2][64][64]  = 96 KB, XOR swizzled.
// ============================================================================
#define ATTN_SMEM 98304

__global__ __launch_bounds__(128, 1)
void attn_mma(const __nv_bfloat16* __restrict__ Qh, const __nv_bfloat16* __restrict__ Ql,
              const __nv_bfloat16* __restrict__ Kh, const __nv_bfloat16* __restrict__ Kl,
              const __nv_bfloat16* __restrict__ Vh, const __nv_bfloat16* __restrict__ Vl,
              float* __restrict__ ctx)
{
    extern __shared__ __align__(128) char smem[];
    const uint32_t sb = smem_u32(smem);
    const int tid = threadIdx.x, lane = tid & 31, w = tid >> 5;
    const int q0 = blockIdx.x * 128;
    const int bh = blockIdx.y;
    const size_t base = (size_t)bh * L_ * HD_;

    const uint32_t QHs = sb, QLs = sb + 16384;
    const uint32_t KHs = sb + 32768, KLs = sb + 49152;
    const uint32_t VHs = sb + 65536, VLs = sb + 81920;

    const int lr = tid >> 3, lg = tid & 7;

    // Q tiles (persist whole kernel)
#pragma unroll
    for (int j = 0; j < 16; j++) {
        const int arr = j >> 3;                       // 0: hi, 1: lo
        const int r = 16 * (j & 7) + lr;              // 0..127
        const uint32_t dst = (arr ? QLs : QHs) + r * 128 + ((lg ^ (r & 7)) << 4);
        const __nv_bfloat16* src = (arr ? Ql : Qh) + base + (size_t)(q0 + r) * HD_ + lg * 8;
        cp16(dst, src);
    }
    auto issueKV = [&](int t, int s) {
        const uint32_t bases[4] = {KHs + s * 8192, KLs + s * 8192,
                                   VHs + s * 8192, VLs + s * 8192};
        const __nv_bfloat16* srcs[4] = {Kh, Kl, Vh, Vl};
#pragma unroll
        for (int j = 0; j < 16; j++) {
            const int arr = j >> 2;                   // 4 arrays x 4 row-groups
            const int r = 16 * (j & 3) + lr;          // 0..63
            cp16(bases[arr] + r * 128 + ((lg ^ (r & 7)) << 4),
                 srcs[arr] + base + (size_t)(t * 64 + r) * HD_ + lg * 8);
        }
    };
    issueKV(0, 0);
    CPCOMMIT();

    float o[2][8][4];
#pragma unroll
    for (int i = 0; i < 2; i++)
#pragma unroll
        for (int j = 0; j < 8; j++)
#pragma unroll
            for (int k = 0; k < 4; k++) o[i][j][k] = 0.f;
    float mrow[2][2] = {{-1e30f, -1e30f}, {-1e30f, -1e30f}};
    float lrow[2][2] = {{0.f, 0.f}, {0.f, 0.f}};

    for (int t = 0; t < 32; t++) {
        __syncthreads();                               // all done with stage (t+1)&1
        if (t + 1 < 32) issueKV(t + 1, (t + 1) & 1);
        CPCOMMIT();
        CPWAIT(1);                                     // tile t resident
        __syncthreads();
        const int s = t & 1;
        const uint32_t kh_b = KHs + s * 8192, kl_b = KLs + s * 8192;
        const uint32_t vh_b = VHs + s * 8192, vl_b = VLs + s * 8192;

        // ---- S = Q . K^T (3-term split) ----
        float sc[2][8][4];
#pragma unroll
        for (int i = 0; i < 2; i++)
#pragma unroll
            for (int j = 0; j < 8; j++)
#pragma unroll
                for (int k = 0; k < 4; k++) sc[i][j][k] = 0.f;

#pragma unroll
        for (int kk = 0; kk < 4; kk++) {
            const int g = 2 * kk + (lane >> 4);
            uint32_t qhf[2][4], qlf[2][4];
#pragma unroll
            for (int mt = 0; mt < 2; mt++) {
                const int r = w * 32 + 16 * mt + (lane & 15);
                const uint32_t off = r * 128 + ((g ^ (r & 7)) << 4);
                ldsm4(qhf[mt], QHs + off);
                ldsm4(qlf[mt], QLs + off);
            }
#pragma unroll
            for (int ntp = 0; ntp < 4; ntp++) {
                const int r = 16 * ntp + (lane & 15);
                const uint32_t off = r * 128 + ((g ^ (r & 7)) << 4);
                uint32_t khf[4], klf[4];
                ldsm4(khf, kh_b + off);
                ldsm4(klf, kl_b + off);
#pragma unroll
                for (int mt = 0; mt < 2; mt++) {
                    mma16816(sc[mt][2*ntp],   qhf[mt], khf[0], khf[2]);
                    mma16816(sc[mt][2*ntp+1], qhf[mt], khf[1], khf[3]);
                    mma16816(sc[mt][2*ntp],   qlf[mt], khf[0], khf[2]);
                    mma16816(sc[mt][2*ntp+1], qlf[mt], khf[1], khf[3]);
                    mma16816(sc[mt][2*ntp],   qhf[mt], klf[0], klf[2]);
                    mma16816(sc[mt][2*ntp+1], qhf[mt], klf[1], klf[3]);
                }
            }
        }

        // ---- online softmax (rows live in quads: reduce over lane^1, lane^2) ----
#pragma unroll
        for (int mt = 0; mt < 2; mt++)
#pragma unroll
            for (int h = 0; h < 2; h++) {
                float tm = -1e30f;
#pragma unroll
                for (int nt = 0; nt < 8; nt++)
                    tm = fmaxf(tm, fmaxf(sc[mt][nt][2*h], sc[mt][nt][2*h+1]));
                tm = fmaxf(tm, __shfl_xor_sync(0xffffffffu, tm, 1));
                tm = fmaxf(tm, __shfl_xor_sync(0xffffffffu, tm, 2));
                const float mn = fmaxf(mrow[mt][h], tm);
                const float corr = __expf(mrow[mt][h] - mn);
                mrow[mt][h] = mn;
                float rs = 0.f;
#pragma unroll
                for (int nt = 0; nt < 8; nt++) {
                    const float p0 = __expf(sc[mt][nt][2*h]   - mn);
                    const float p1 = __expf(sc[mt][nt][2*h+1] - mn);
                    sc[mt][nt][2*h] = p0; sc[mt][nt][2*h+1] = p1;
                    rs += p0 + p1;
                }
                rs += __shfl_xor_sync(0xffffffffu, rs, 1);
                rs += __shfl_xor_sync(0xffffffffu, rs, 2);
                lrow[mt][h] = lrow[mt][h] * corr + rs;
#pragma unroll
                for (int nt = 0; nt < 8; nt++) {
                    o[mt][nt][2*h]   *= corr;
                    o[mt][nt][2*h+1] *= corr;
                }
            }

        // ---- O += P . V : P built in registers from sc ----
#pragma unroll
        for (int kk = 0; kk < 4; kk++) {
            uint32_t pah[2][4], pal[2][4];
#pragma unroll
            for (int mt = 0; mt < 2; mt++) {
                const float* s0 = sc[mt][2*kk];
                const float* s1 = sc[mt][2*kk+1];
                // hi packs: a0=(row g, k0k1), a1=(row g+8, k0k1), a2=(row g, k8k9), a3=(g+8,k8k9)
                pah[mt][0] = pack_bf2(s0[1], s0[0]);
                pah[mt][1] = pack_bf2(s0[3], s0[2]);
                pah[mt][2] = pack_bf2(s1[1], s1[0]);
                pah[mt][3] = pack_bf2(s1[3], s1[2]);
#pragma unroll
                for (int q = 0; q < 4; q++) {
                    const float* sp = (q < 2) ? s0 : s1;
                    const int e = (q & 1) * 2;
                    const uint32_t hv = pah[mt][q];
                    const float flo = __uint_as_float(hv << 16);
                    const float fhi = __uint_as_float(hv & 0xffff0000u);
                    pal[mt][q] = pack_bf2(sp[e + 1] - fhi, sp[e] - flo);
                }
            }
#pragma unroll
            for (int ntp = 0; ntp < 4; ntp++) {
                const int kr = 16 * kk + ((lane >> 3) & 1) * 8 + (lane & 7);
                const int g = 2 * ntp + (lane >> 4);
                const uint32_t off = kr * 128 + ((g ^ (kr & 7)) << 4);
                uint32_t vhf[4], vlf[4];
                ldsm4t(vhf, vh_b + off);
                ldsm4t(vlf, vl_b + off);
#pragma unroll
                for (int mt = 0; mt < 2; mt++) {
                    mma16816(o[mt][2*ntp],   pah[mt], vhf[0], vhf[1]);
                    mma16816(o[mt][2*ntp+1], pah[mt], vhf[2], vhf[3]);
                    mma16816(o[mt][2*ntp],   pal[mt], vhf[0], vhf[1]);
                    mma16816(o[mt][2*ntp+1], pal[mt], vhf[2], vhf[3]);
                    mma16816(o[mt][2*ntp],   pah[mt], vlf[0], vlf[1]);
                    mma16816(o[mt][2*ntp+1], pah[mt], vlf[2], vlf[3]);
                }
            }
        }
    }

    // ---- epilogue: normalize + write ctx [B,L,D] head-interleaved ----
    const int b = bh >> 4, head = bh & 15;
#pragma unroll
    for (int mt = 0; mt < 2; mt++)
#pragma unroll
        for (int h = 0; h < 2; h++) {
            const float inv = 1.f / lrow[mt][h];
            const int qr = q0 + w * 32 + 16 * mt + 8 * h + (lane >> 2);
            float* dst = ctx + ((size_t)(b * L_ + qr)) * D_ + head * HD_ + (lane & 3) * 2;
#pragma unroll
            for (int nt = 0; nt < 8; nt++) {
                float2 v = {o[mt][nt][2*h] * inv, o[mt][nt][2*h+1] * inv};
                *(float2*)(dst + 8 * nt) = v;
            }
        }
}

// ============================================================================
// launch
// ============================================================================
extern "C" void kernel_launch(void* const* d_in, const int* in_sizes, int n_in,
                              void* d_out, int out_size)
{
    const float* query = (const float*)d_in[0];
    const float* key_  = (const float*)d_in[1];
    const float* value = (const float*)d_in[2];
    const float* Wq = (const float*)d_in[3];
    const float* bq = (const float*)d_in[4];
    const float* Wk = (const float*)d_in[5];
    const float* bk = (const float*)d_in[6];
    const float* Wv = (const float*)d_in[7];
    const float* bv = (const float*)d_in[8];
    const float* Wo = (const float*)d_in[9];
    const float* bo = (const float*)d_in[10];
    float* out = (float*)d_out;

    float *Ctx;
    __nv_bfloat16 *Ab, *Wt, *Qh, *Ql, *Kh, *Kl, *Vh, *Vl;
    cudaGetSymbolAddress((void**)&Ctx, g_ctx);
    cudaGetSymbolAddress((void**)&Ab,  g_A);
    cudaGetSymbolAddress((void**)&Wt,  g_Wt);
    cudaGetSymbolAddress((void**)&Qh,  g_Qh);
    cudaGetSymbolAddress((void**)&Ql,  g_Ql);
    cudaGetSymbolAddress((void**)&Kh,  g_Kh);
    cudaGetSymbolAddress((void**)&Kl,  g_Kl);
    cudaGetSymbolAddress((void**)&Vh,  g_Vh);
    cudaGetSymbolAddress((void**)&Vl,  g_Vl);
    __nv_bfloat16* Wt0 = Wt;
    __nv_bfloat16* Wt1 = Wt + (size_t)1 * D_ * KSPLIT;
    __nv_bfloat16* Wt2 = Wt + (size_t)2 * D_ * KSPLIT;
    __nv_bfloat16* Wt3 = Wt + (size_t)3 * D_ * KSPLIT;

    cudaFuncSetAttribute(gemm_mma<0>, cudaFuncAttributeMaxDynamicSharedMemorySize, G_SMEM);
    cudaFuncSetAttribute(gemm_mma<1>, cudaFuncAttributeMaxDynamicSharedMemorySize, G_SMEM);
    cudaFuncSetAttribute(attn_mma, cudaFuncAttributeMaxDynamicSharedMemorySize, ATTN_SMEM);

    dim3 wg(32, 32), wb(32, 8);
    split_weightT<<<wg, wb>>>(Wq, Wt0);
    split_weightT<<<wg, wb>>>(Wk, Wt1);
    split_weightT<<<wg, wb>>>(Wv, Wt2);
    split_weightT<<<wg, wb>>>(Wo, Wt3);

    dim3 gg(D_ / 128, MROWS / 256);   // (8, 16) = 128 CTAs
    const int srb = MROWS * D_ / 1024;

    split_rows<<<srb, 256>>>(query, Ab);
    gemm_mma<1><<<gg, 512, G_SMEM>>>(Ab, Wt0, bq, nullptr, Qh, Ql, 0.125f);
    split_rows<<<srb, 256>>>(key_, Ab);
    gemm_mma<1><<<gg, 512, G_SMEM>>>(Ab, Wt1, bk, nullptr, Kh, Kl, 1.0f);
    split_rows<<<srb, 256>>>(value, Ab);
    gemm_mma<1><<<gg, 512, G_SMEM>>>(Ab, Wt2, bv, nullptr, Vh, Vl, 1.0f);

    dim3 ag(L_ / 128, B_ * H_);       // (16, 32)
    attn_mma<<<ag, 128, ATTN_SMEM>>>(Qh, Ql, Kh, Kl, Vh, Vl, Ctx);

    split_rows<<<srb, 256>>>(Ctx, Ab);
    gemm_mma<0><<<gg, 512, G_SMEM>>>(Ab, Wt3, bo, out, nullptr, nullptr, 1.0f);
}